// round 14
// baseline (speedup 1.0000x reference)
#include <cuda_runtime.h>
#include <cuda_fp16.h>
#include <math.h>
#include <stdint.h>

#define B_  4
#define N_  2048
#define D_  1024
#define E_  8
#define H_  4096
#define C_  320
#define BN_TOK (B_*N_)

// -------- scratch (device globals: allocation-free) --------
__device__ __half g_Yh[(size_t)B_*E_*C_*H_];   // expert hidden, fp16
__device__ __half g_xh[(size_t)BN_TOK*D_];     // x in fp16
__device__ __half g_w1t[(size_t)E_*H_*D_];     // w1 transposed: [E][H][D] fp16 (K-major)
__device__ __half g_w2t[(size_t)E_*D_*H_];     // w2 transposed: [E][D][H] fp16 (K-major)
__device__ int    g_s2t[B_*E_*C_];
__device__ int    g_cnt[B_*E_];
__device__ float  g_proxy[B_*E_];
__device__ float  g_gate[BN_TOK];
__device__ int    g_idx[BN_TOK];
__device__ float  g_z2;

// ---------------- helpers ----------------
__device__ __forceinline__ void mma16(float c[4], const unsigned a[4], const unsigned b[2]) {
    asm volatile("mma.sync.aligned.m16n8k16.row.col.f32.f16.f16.f32 "
                 "{%0,%1,%2,%3},{%4,%5,%6,%7},{%8,%9},{%0,%1,%2,%3};"
                 : "+f"(c[0]), "+f"(c[1]), "+f"(c[2]), "+f"(c[3])
                 : "r"(a[0]), "r"(a[1]), "r"(a[2]), "r"(a[3]), "r"(b[0]), "r"(b[1]));
}
__device__ __forceinline__ void ldsm4(unsigned& r0, unsigned& r1, unsigned& r2, unsigned& r3,
                                      unsigned addr) {
    asm volatile("ldmatrix.sync.aligned.m8n8.x4.shared.b16 {%0,%1,%2,%3}, [%4];"
                 : "=r"(r0), "=r"(r1), "=r"(r2), "=r"(r3) : "r"(addr));
}
__device__ __forceinline__ void cp16(unsigned saddr, const void* g, int sz) {
    asm volatile("cp.async.cg.shared.global [%0], [%1], 16, %2;"
                 :: "r"(saddr), "l"(g), "r"(sz));
}
__device__ __forceinline__ void cpcommit() { asm volatile("cp.async.commit_group;"); }
template<int n> __device__ __forceinline__ void cpwait() {
    asm volatile("cp.async.wait_group %0;" :: "n"(n));
}
// fast gelu (tanh approx via __expf; matches jax tanh-gelu to ~1e-6)
__device__ __forceinline__ float gelu_tanh(float v) {
    float u = 0.7978845608028654f * v * (1.f + 0.044715f * v * v);
    float th = 1.f - 2.f / (__expf(2.f * u) + 1.f);
    return 0.5f * v * (1.f + th);
}

// ---------------- init ----------------
__global__ void k_init() {
    int i = blockIdx.x * blockDim.x + threadIdx.x;
    if (i < B_*E_*C_) g_s2t[i] = -1;
    if (i < B_*E_)    g_proxy[i] = 0.f;
    if (i == 0)       g_z2 = 0.f;
}

// ---------------- weight transposes -> fp16 K-major ----------------
__global__ void __launch_bounds__(128) k_tr1(const float* __restrict__ w) {
    __shared__ float s[32][33];
    int e = blockIdx.z, h0 = blockIdx.x*32, d0 = blockIdx.y*32;
    const float* S = w + (size_t)e * D_ * H_;
    int tid = threadIdx.x;
#pragma unroll
    for (int it = 0; it < 2; it++) {
        int dr = (tid >> 3) + it*16;
        int hc = (tid & 7) * 4;
        float4 v = *(const float4*)&S[(size_t)(d0+dr)*H_ + h0 + hc];
        s[dr][hc] = v.x; s[dr][hc+1] = v.y; s[dr][hc+2] = v.z; s[dr][hc+3] = v.w;
    }
    __syncthreads();
    int hp = tid >> 2, o = tid & 3;
    __align__(16) __half hb[8];
#pragma unroll
    for (int j = 0; j < 8; j++) hb[j] = __float2half(s[o*8 + j][hp]);
    *(uint4*)&g_w1t[(size_t)e*H_*D_ + (size_t)(h0+hp)*D_ + d0 + o*8] = *(uint4*)hb;
}
__global__ void __launch_bounds__(128) k_tr2(const float* __restrict__ w) {
    __shared__ float s[32][33];
    int e = blockIdx.z, d0 = blockIdx.x*32, h0 = blockIdx.y*32;
    const float* S = w + (size_t)e * H_ * D_;
    int tid = threadIdx.x;
#pragma unroll
    for (int it = 0; it < 2; it++) {
        int hr = (tid >> 3) + it*16;
        int dc = (tid & 7) * 4;
        float4 v = *(const float4*)&S[(size_t)(h0+hr)*D_ + d0 + dc];
        s[hr][dc] = v.x; s[hr][dc+1] = v.y; s[hr][dc+2] = v.z; s[hr][dc+3] = v.w;
    }
    __syncthreads();
    int dp = tid >> 2, o = tid & 3;
    __align__(16) __half hb[8];
#pragma unroll
    for (int j = 0; j < 8; j++) hb[j] = __float2half(s[o*8 + j][dp]);
    *(uint4*)&g_w2t[(size_t)e*D_*H_ + (size_t)(d0+dp)*H_ + h0 + o*8] = *(uint4*)hb;
}

// ---------------- router: warp per token, block-aggregated atomics ----------------
#define RTOK 16
__global__ void __launch_bounds__(512) k_router(const float* __restrict__ x,
                                                const float* __restrict__ wr) {
    __shared__ float swr[8][1024];
    __shared__ float sproxy[8];
    __shared__ float sz2;
    int tid = threadIdx.x;
    for (int d = tid; d < 1024; d += 512) {
        float4 a = *(const float4*)&wr[d*8];
        float4 b = *(const float4*)&wr[d*8 + 4];
        swr[0][d] = a.x; swr[1][d] = a.y; swr[2][d] = a.z; swr[3][d] = a.w;
        swr[4][d] = b.x; swr[5][d] = b.y; swr[6][d] = b.z; swr[7][d] = b.w;
    }
    if (tid < 8) sproxy[tid] = 0.f;
    if (tid == 8) sz2 = 0.f;
    __syncthreads();

    int warp = tid >> 5, lane = tid & 31;
    int t = blockIdx.x * RTOK + warp;
    int b = t / N_;
    const float* xr = x + (size_t)t * D_;
    __half* xtr = g_xh + (size_t)t * D_;

    float acc[8];
#pragma unroll
    for (int e = 0; e < 8; e++) acc[e] = 0.f;
#pragma unroll
    for (int i = 0; i < 8; i++) {
        int d = i*128 + lane*4;
        float4 xv = __ldg((const float4*)(xr + d));
        __align__(8) __half2 hh[2];
        hh[0] = __floats2half2_rn(xv.x, xv.y);
        hh[1] = __floats2half2_rn(xv.z, xv.w);
        *(uint2*)(xtr + d) = *(uint2*)hh;
#pragma unroll
        for (int e = 0; e < 8; e++) {
            float4 w = *(const float4*)&swr[e][d];
            acc[e] += xv.x*w.x + xv.y*w.y + xv.z*w.z + xv.w*w.w;
        }
    }
#pragma unroll
    for (int e = 0; e < 8; e++)
#pragma unroll
        for (int off = 16; off > 0; off >>= 1)
            acc[e] += __shfl_xor_sync(0xffffffffu, acc[e], off);

    if (lane == 0) {
        float maxl = acc[0]; int amax = 0;
#pragma unroll
        for (int e = 1; e < 8; e++) if (acc[e] > maxl) { maxl = acc[e]; amax = e; }
        float sum = 0.f, p[8];
#pragma unroll
        for (int e = 0; e < 8; e++) { p[e] = expf(acc[e] - maxl); sum += p[e]; }
        float inv = 1.f / sum;
        float z = maxl + logf(sum);
#pragma unroll
        for (int e = 0; e < 8; e++) atomicAdd(&sproxy[e], p[e] * inv);
        atomicAdd(&sz2, z * z);
        g_idx[t]  = amax;
        g_gate[t] = p[amax] * inv;
    }
    __syncthreads();
    if (tid < 8)  atomicAdd(&g_proxy[b*8 + tid], sproxy[tid]);
    if (tid == 8) atomicAdd(&g_z2, sz2);
}

// ---------------- capacity scan ----------------
__global__ void k_scan() {
    int be = blockIdx.x;
    int b = be / E_, e = be % E_;
    int lane = threadIdx.x;
    unsigned lt = (1u << lane) - 1u;
    int base = 0;
    for (int n0 = 0; n0 < N_; n0 += 256) {
        int v[8];
#pragma unroll
        for (int u = 0; u < 8; u++) v[u] = __ldg(&g_idx[b*N_ + n0 + u*32 + lane]);
#pragma unroll
        for (int u = 0; u < 8; u++) {
            int pred = (v[u] == e);
            unsigned bal = __ballot_sync(0xffffffffu, pred);
            if (pred) {
                int slot = base + __popc(bal & lt);
                if (slot < C_) g_s2t[be*C_ + slot] = n0 + u*32 + lane;
            }
            base += __popc(bal);
        }
    }
    if (lane == 0) g_cnt[be] = base;
}

// ---------------- scalar losses (parallel) ----------------
__global__ void k_final(float* __restrict__ out) {
    int i = threadIdx.x;
    float v = ((float)g_cnt[i] / (float)N_) * (g_proxy[i] / (float)N_);
#pragma unroll
    for (int off = 16; off > 0; off >>= 1) v += __shfl_xor_sync(0xffffffffu, v, off);
    if (i == 0) {
        out[(size_t)BN_TOK * D_]     = v * (float)(E_*E_) / (float)B_;
        out[(size_t)BN_TOK * D_ + 1] = g_z2 / (float)BN_TOK;
    }
}

// ---------------- fp16 mma GEMM: BM=64 BN=128 BK=32, 4 warps (2x2), warp 32x64 ----------------
// ldmatrix fragment loads; beOff allows split launches for cross-stream tail fusion
#define PA 40   // pitch in halves (80 bytes)

template<bool IS_G1, int OCC>
__global__ void __launch_bounds__(128, OCC) k_mma(const float* __restrict__ bias,
                                                  float* __restrict__ outp, int beOff)
{
    constexpr int KDIM  = IS_G1 ? D_ : H_;
    constexpr int ITERS = KDIM / 32;
    constexpr int AS_H = 64*PA, BS_H = 128*PA;

    __shared__ __align__(16) __half As[3*AS_H];
    __shared__ __align__(16) __half Bs[3*BS_H];
    __shared__ int tok[64];

    int be = blockIdx.z + beOff, b = be >> 3, e = be & 7;
    int m0 = blockIdx.y * 64, n0 = blockIdx.x * 128;
    int tid = threadIdx.x, lane = tid & 31, wid = tid >> 5;

    // skip fully-empty capacity tiles
    if (__ldg(&g_cnt[be]) <= m0) return;

    if (tid < 64) tok[tid] = g_s2t[be*C_ + m0 + tid];
    __syncthreads();

    int ar0 = tid >> 2, ar1 = ar0 + 32, akc = tid & 3;
    int br0 = tid >> 2, bkc = tid & 3;

    const __half* aS0; const __half* aS1; int az0, az1;
    if (IS_G1) {
        int t0 = tok[ar0], t1 = tok[ar1];
        aS0 = (t0 >= 0) ? g_xh + ((size_t)(b*N_ + t0) * D_ + akc*8) : g_xh;
        aS1 = (t1 >= 0) ? g_xh + ((size_t)(b*N_ + t1) * D_ + akc*8) : g_xh;
        az0 = (t0 >= 0) ? 16 : 0;  az1 = (t1 >= 0) ? 16 : 0;
    } else {
        int t0 = tok[ar0], t1 = tok[ar1];
        aS0 = g_Yh + ((size_t)be*C_ + m0 + ar0) * H_ + akc*8;
        aS1 = g_Yh + ((size_t)be*C_ + m0 + ar1) * H_ + akc*8;
        az0 = (t0 >= 0) ? 16 : 0;  az1 = (t1 >= 0) ? 16 : 0;
    }
    const __half* wt = IS_G1 ? g_w1t : g_w2t;
    const __half* wbase = wt + (size_t)e * (IS_G1 ? (size_t)H_*D_ : (size_t)D_*H_)
                        + (size_t)(n0 + br0) * KDIM + bkc*8;

    unsigned saAs = (unsigned)__cvta_generic_to_shared(As);
    unsigned saBs = (unsigned)__cvta_generic_to_shared(Bs);
    unsigned saA0 = saAs + (ar0*PA + akc*8)*2;
    unsigned saA1 = saAs + (ar1*PA + akc*8)*2;
    unsigned saB0 = saBs + (br0*PA + bkc*8)*2;
    constexpr unsigned A_ST = AS_H*2, B_ST = BS_H*2;

    auto fill = [&](int st, int k0) {
        cp16(saA0 + st*A_ST, aS0 + k0, az0);
        cp16(saA1 + st*A_ST, aS1 + k0, az1);
#pragma unroll
        for (int j = 0; j < 4; j++)
            cp16(saB0 + st*B_ST + j*32*PA*2, wbase + (size_t)32*j*KDIM + k0, 16);
        cpcommit();
    };

    float acc[2][8][4];
#pragma unroll
    for (int i = 0; i < 2; i++)
#pragma unroll
        for (int j = 0; j < 8; j++)
#pragma unroll
            for (int k = 0; k < 4; k++) acc[i][j][k] = 0.f;

    fill(0, 0);
    fill(1, 32);

    int wm = wid & 1, wn = wid >> 1;

    unsigned offA = ((unsigned)((lane & 7) + ((lane >> 3) & 1) * 8) * PA
                   + (unsigned)((lane >> 4) & 1) * 8) * 2;
    unsigned offB = ((unsigned)((lane & 7) + ((lane >> 4) & 1) * 8) * PA
                   + (unsigned)((lane >> 3) & 1) * 8) * 2;

    for (int it = 0; it < ITERS; ++it) {
        int cur = it % 3;
        cpwait<1>();
        __syncthreads();

        int nxt = it + 2;
        if (nxt < ITERS) fill(nxt % 3, nxt * 32);
        else cpcommit();

        unsigned baseA = saAs + cur*A_ST + offA;
        unsigned baseB = saBs + cur*B_ST + offB;
#pragma unroll
        for (int s = 0; s < 2; s++) {
            unsigned a[2][4], bf[8][2];
            unsigned ks = (unsigned)(s*16) * 2;
#pragma unroll
            for (int mt = 0; mt < 2; mt++) {
                unsigned ad = baseA + (unsigned)((wm*32 + mt*16) * PA) * 2 + ks;
                ldsm4(a[mt][0], a[mt][1], a[mt][2], a[mt][3], ad);
            }
#pragma unroll
            for (int j = 0; j < 4; j++) {
                unsigned bd = baseB + (unsigned)((wn*64 + j*16) * PA) * 2 + ks;
                ldsm4(bf[2*j][0], bf[2*j][1], bf[2*j+1][0], bf[2*j+1][1], bd);
            }
#pragma unroll
            for (int mt = 0; mt < 2; mt++)
#pragma unroll
                for (int nt = 0; nt < 8; nt++) mma16(acc[mt][nt], a[mt], bf[nt]);
        }
    }

    // ---------------- epilogue ----------------
    int gq = lane >> 2, t4 = lane & 3;
    if (IS_G1) {
#pragma unroll
        for (int mt = 0; mt < 2; mt++) {
            int r1 = m0 + wm*32 + mt*16 + gq, r2 = r1 + 8;
#pragma unroll
            for (int nt = 0; nt < 8; nt++) {
                int gn = n0 + wn*64 + nt*8 + 2*t4;
                float2 bv = *(const float2*)&bias[(size_t)e*H_ + gn];
                __half2 v1, v2;
                v1.x = __float2half(gelu_tanh(acc[mt][nt][0] + bv.x));
                v1.y = __float2half(gelu_tanh(acc[mt][nt][1] + bv.y));
                v2.x = __float2half(gelu_tanh(acc[mt][nt][2] + bv.x));
                v2.y = __float2half(gelu_tanh(acc[mt][nt][3] + bv.y));
                *(__half2*)&g_Yh[((size_t)be*C_ + r1)*H_ + gn] = v1;
                *(__half2*)&g_Yh[((size_t)be*C_ + r2)*H_ + gn] = v2;
            }
        }
    } else {
#pragma unroll
        for (int mt = 0; mt < 2; mt++) {
            int r = wm*32 + mt*16 + gq;
            int tk1 = tok[r], tk2 = tok[r + 8];
            float gv1 = (tk1 >= 0) ? g_gate[b*N_ + tk1] : 0.f;
            float gv2 = (tk2 >= 0) ? g_gate[b*N_ + tk2] : 0.f;
#pragma unroll
            for (int nt = 0; nt < 8; nt++) {
                int gn = n0 + wn*64 + nt*8 + 2*t4;
                float2 bv = *(const float2*)&bias[(size_t)e*D_ + gn];
                if (tk1 >= 0) {
                    float2 v = { gv1*(acc[mt][nt][0] + bv.x), gv1*(acc[mt][nt][1] + bv.y) };
                    *(float2*)&outp[((size_t)(b*N_ + tk1))*D_ + gn] = v;
                }
                if (tk2 >= 0) {
                    float2 v = { gv2*(acc[mt][nt][2] + bv.x), gv2*(acc[mt][nt][3] + bv.y) };
                    *(float2*)&outp[((size_t)(b*N_ + tk2))*D_ + gn] = v;
                }
            }
        }
    }
}

// ---------------- launch: fork-join + split GEMMs for cross-stream tail fusion ----------------
extern "C" void kernel_launch(void* const* d_in, const int* in_sizes, int n_in,
                              void* d_out, int out_size) {
    const float* x  = (const float*)d_in[0];
    const float* wr = (const float*)d_in[1];
    const float* w1 = (const float*)d_in[2];
    const float* b1 = (const float*)d_in[3];
    const float* w2 = (const float*)d_in[4];
    const float* b2 = (const float*)d_in[5];
    float* out = (float*)d_out;

    static cudaStream_t s1 = nullptr, s2 = nullptr;
    static cudaEvent_t ev0 = nullptr, ev_t1 = nullptr, ev_t2 = nullptr, ev_ms = nullptr,
                       ev_g1a = nullptr, ev_g2a = nullptr;
    if (!s1) {
        cudaStreamCreateWithFlags(&s1, cudaStreamNonBlocking);
        cudaStreamCreateWithFlags(&s2, cudaStreamNonBlocking);
        cudaEventCreateWithFlags(&ev0,    cudaEventDisableTiming);
        cudaEventCreateWithFlags(&ev_t1,  cudaEventDisableTiming);
        cudaEventCreateWithFlags(&ev_t2,  cudaEventDisableTiming);
        cudaEventCreateWithFlags(&ev_ms,  cudaEventDisableTiming);
        cudaEventCreateWithFlags(&ev_g1a, cudaEventDisableTiming);
        cudaEventCreateWithFlags(&ev_g2a, cudaEventDisableTiming);
    }

    // fork
    cudaEventRecord(ev0, 0);

    // branch A (s1): weight transposes
    cudaStreamWaitEvent(s1, ev0, 0);
    k_tr1<<<dim3(H_/32, D_/32, E_), 128, 0, s1>>>(w1);
    cudaEventRecord(ev_t1, s1);
    k_tr2<<<dim3(D_/32, H_/32, E_), 128, 0, s1>>>(w2);
    cudaEventRecord(ev_t2, s1);

    // branch B (s2): zero the output tensor region
    cudaStreamWaitEvent(s2, ev0, 0);
    cudaMemsetAsync(out, 0, (size_t)BN_TOK * D_ * sizeof(float), s2);
    cudaEventRecord(ev_ms, s2);

    // main chain (stream 0): routing
    k_init<<<(B_*E_*C_ + 255) / 256, 256>>>();
    k_router<<<BN_TOK/RTOK, 512>>>(x, wr);
    k_scan<<<B_*E_, 32>>>();
    k_final<<<1, 32>>>(out);

    // GEMM1 split: first half then second half (stream 0)
    cudaStreamWaitEvent(0, ev_t1, 0);
    k_mma<true,  2><<<dim3(H_/128, C_/64, 16), 128>>>(b1, nullptr, 0);
    cudaEventRecord(ev_g1a, 0);
    k_mma<true,  2><<<dim3(H_/128, C_/64, 16), 128>>>(b1, nullptr, 16);

    // GEMM2 first half on s2 — overlaps GEMM1's second half
    cudaStreamWaitEvent(s2, ev_g1a, 0);
    cudaStreamWaitEvent(s2, ev_t2, 0);
    k_mma<false, 3><<<dim3(D_/128, C_/64, 16), 128, 0, s2>>>(b2, out, 0);
    cudaEventRecord(ev_g2a, s2);

    // GEMM2 second half on stream 0 (after GEMM1b; needs tr2 + memset)
    cudaStreamWaitEvent(0, ev_t2, 0);
    cudaStreamWaitEvent(0, ev_ms, 0);
    k_mma<false, 3><<<dim3(D_/128, C_/64, 16), 128>>>(b2, out, 16);

    // join
    cudaStreamWaitEvent(0, ev_g2a, 0);
}

// round 15
// speedup vs baseline: 1.0098x; 1.0098x over previous
#include <cuda_runtime.h>
#include <cuda_fp16.h>
#include <math.h>
#include <stdint.h>

#define B_  4
#define N_  2048
#define D_  1024
#define E_  8
#define H_  4096
#define C_  320
#define BN_TOK (B_*N_)

// -------- scratch (device globals: allocation-free) --------
__device__ __half g_Yh[(size_t)B_*E_*C_*H_];   // expert hidden, fp16
__device__ __half g_xh[(size_t)BN_TOK*D_];     // x in fp16
__device__ __half g_w1t[(size_t)E_*H_*D_];     // w1 transposed: [E][H][D] fp16 (K-major)
__device__ __half g_w2t[(size_t)E_*D_*H_];     // w2 transposed: [E][D][H] fp16 (K-major)
__device__ int    g_s2t[B_*E_*C_];
__device__ int    g_cnt[B_*E_];
__device__ float  g_proxy[B_*E_];
__device__ float  g_gate[BN_TOK];
__device__ int    g_idx[BN_TOK];
__device__ float  g_z2;

// ---------------- helpers ----------------
__device__ __forceinline__ void mma16(float c[4], const unsigned a[4], const unsigned b[2]) {
    asm volatile("mma.sync.aligned.m16n8k16.row.col.f32.f16.f16.f32 "
                 "{%0,%1,%2,%3},{%4,%5,%6,%7},{%8,%9},{%0,%1,%2,%3};"
                 : "+f"(c[0]), "+f"(c[1]), "+f"(c[2]), "+f"(c[3])
                 : "r"(a[0]), "r"(a[1]), "r"(a[2]), "r"(a[3]), "r"(b[0]), "r"(b[1]));
}
__device__ __forceinline__ void ldsm4(unsigned& r0, unsigned& r1, unsigned& r2, unsigned& r3,
                                      unsigned addr) {
    asm volatile("ldmatrix.sync.aligned.m8n8.x4.shared.b16 {%0,%1,%2,%3}, [%4];"
                 : "=r"(r0), "=r"(r1), "=r"(r2), "=r"(r3) : "r"(addr));
}
__device__ __forceinline__ void cp16(unsigned saddr, const void* g, int sz) {
    asm volatile("cp.async.cg.shared.global [%0], [%1], 16, %2;"
                 :: "r"(saddr), "l"(g), "r"(sz));
}
__device__ __forceinline__ void cpcommit() { asm volatile("cp.async.commit_group;"); }
template<int n> __device__ __forceinline__ void cpwait() {
    asm volatile("cp.async.wait_group %0;" :: "n"(n));
}
// fast gelu (tanh approx via __expf; matches jax tanh-gelu to ~1e-6)
__device__ __forceinline__ float gelu_tanh(float v) {
    float u = 0.7978845608028654f * v * (1.f + 0.044715f * v * v);
    float th = 1.f - 2.f / (__expf(2.f * u) + 1.f);
    return 0.5f * v * (1.f + th);
}

// ---------------- init ----------------
__global__ void k_init() {
    int i = blockIdx.x * blockDim.x + threadIdx.x;
    if (i < B_*E_*C_) g_s2t[i] = -1;
    if (i < B_*E_)    g_proxy[i] = 0.f;
    if (i == 0)       g_z2 = 0.f;
}

// ---------------- weight transposes -> fp16 K-major ----------------
__global__ void __launch_bounds__(128) k_tr1(const float* __restrict__ w) {
    __shared__ float s[32][33];
    int e = blockIdx.z, h0 = blockIdx.x*32, d0 = blockIdx.y*32;
    const float* S = w + (size_t)e * D_ * H_;
    int tid = threadIdx.x;
#pragma unroll
    for (int it = 0; it < 2; it++) {
        int dr = (tid >> 3) + it*16;
        int hc = (tid & 7) * 4;
        float4 v = *(const float4*)&S[(size_t)(d0+dr)*H_ + h0 + hc];
        s[dr][hc] = v.x; s[dr][hc+1] = v.y; s[dr][hc+2] = v.z; s[dr][hc+3] = v.w;
    }
    __syncthreads();
    int hp = tid >> 2, o = tid & 3;
    __align__(16) __half hb[8];
#pragma unroll
    for (int j = 0; j < 8; j++) hb[j] = __float2half(s[o*8 + j][hp]);
    *(uint4*)&g_w1t[(size_t)e*H_*D_ + (size_t)(h0+hp)*D_ + d0 + o*8] = *(uint4*)hb;
}
__global__ void __launch_bounds__(128) k_tr2(const float* __restrict__ w) {
    __shared__ float s[32][33];
    int e = blockIdx.z, d0 = blockIdx.x*32, h0 = blockIdx.y*32;
    const float* S = w + (size_t)e * H_ * D_;
    int tid = threadIdx.x;
#pragma unroll
    for (int it = 0; it < 2; it++) {
        int hr = (tid >> 3) + it*16;
        int dc = (tid & 7) * 4;
        float4 v = *(const float4*)&S[(size_t)(h0+hr)*D_ + d0 + dc];
        s[hr][dc] = v.x; s[hr][dc+1] = v.y; s[hr][dc+2] = v.z; s[hr][dc+3] = v.w;
    }
    __syncthreads();
    int dp = tid >> 2, o = tid & 3;
    __align__(16) __half hb[8];
#pragma unroll
    for (int j = 0; j < 8; j++) hb[j] = __float2half(s[o*8 + j][dp]);
    *(uint4*)&g_w2t[(size_t)e*D_*H_ + (size_t)(d0+dp)*H_ + h0 + o*8] = *(uint4*)hb;
}

// ---------------- router: warp per token, block-aggregated atomics ----------------
#define RTOK 16
__global__ void __launch_bounds__(512) k_router(const float* __restrict__ x,
                                                const float* __restrict__ wr) {
    __shared__ float swr[8][1024];
    __shared__ float sproxy[8];
    __shared__ float sz2;
    int tid = threadIdx.x;
    for (int d = tid; d < 1024; d += 512) {
        float4 a = *(const float4*)&wr[d*8];
        float4 b = *(const float4*)&wr[d*8 + 4];
        swr[0][d] = a.x; swr[1][d] = a.y; swr[2][d] = a.z; swr[3][d] = a.w;
        swr[4][d] = b.x; swr[5][d] = b.y; swr[6][d] = b.z; swr[7][d] = b.w;
    }
    if (tid < 8) sproxy[tid] = 0.f;
    if (tid == 8) sz2 = 0.f;
    __syncthreads();

    int warp = tid >> 5, lane = tid & 31;
    int t = blockIdx.x * RTOK + warp;
    int b = t / N_;
    const float* xr = x + (size_t)t * D_;
    __half* xtr = g_xh + (size_t)t * D_;

    float acc[8];
#pragma unroll
    for (int e = 0; e < 8; e++) acc[e] = 0.f;
#pragma unroll
    for (int i = 0; i < 8; i++) {
        int d = i*128 + lane*4;
        float4 xv = __ldg((const float4*)(xr + d));
        __align__(8) __half2 hh[2];
        hh[0] = __floats2half2_rn(xv.x, xv.y);
        hh[1] = __floats2half2_rn(xv.z, xv.w);
        *(uint2*)(xtr + d) = *(uint2*)hh;
#pragma unroll
        for (int e = 0; e < 8; e++) {
            float4 w = *(const float4*)&swr[e][d];
            acc[e] += xv.x*w.x + xv.y*w.y + xv.z*w.z + xv.w*w.w;
        }
    }
#pragma unroll
    for (int e = 0; e < 8; e++)
#pragma unroll
        for (int off = 16; off > 0; off >>= 1)
            acc[e] += __shfl_xor_sync(0xffffffffu, acc[e], off);

    if (lane == 0) {
        float maxl = acc[0]; int amax = 0;
#pragma unroll
        for (int e = 1; e < 8; e++) if (acc[e] > maxl) { maxl = acc[e]; amax = e; }
        float sum = 0.f, p[8];
#pragma unroll
        for (int e = 0; e < 8; e++) { p[e] = expf(acc[e] - maxl); sum += p[e]; }
        float inv = 1.f / sum;
        float z = maxl + logf(sum);
#pragma unroll
        for (int e = 0; e < 8; e++) atomicAdd(&sproxy[e], p[e] * inv);
        atomicAdd(&sz2, z * z);
        g_idx[t]  = amax;
        g_gate[t] = p[amax] * inv;
    }
    __syncthreads();
    if (tid < 8)  atomicAdd(&g_proxy[b*8 + tid], sproxy[tid]);
    if (tid == 8) atomicAdd(&g_z2, sz2);
}

// ---------------- capacity scan ----------------
__global__ void k_scan() {
    int be = blockIdx.x;
    int b = be / E_, e = be % E_;
    int lane = threadIdx.x;
    unsigned lt = (1u << lane) - 1u;
    int base = 0;
    for (int n0 = 0; n0 < N_; n0 += 256) {
        int v[8];
#pragma unroll
        for (int u = 0; u < 8; u++) v[u] = __ldg(&g_idx[b*N_ + n0 + u*32 + lane]);
#pragma unroll
        for (int u = 0; u < 8; u++) {
            int pred = (v[u] == e);
            unsigned bal = __ballot_sync(0xffffffffu, pred);
            if (pred) {
                int slot = base + __popc(bal & lt);
                if (slot < C_) g_s2t[be*C_ + slot] = n0 + u*32 + lane;
            }
            base += __popc(bal);
        }
    }
    if (lane == 0) g_cnt[be] = base;
}

// ---------------- scalar losses (parallel) ----------------
__global__ void k_final(float* __restrict__ out) {
    int i = threadIdx.x;
    float v = ((float)g_cnt[i] / (float)N_) * (g_proxy[i] / (float)N_);
#pragma unroll
    for (int off = 16; off > 0; off >>= 1) v += __shfl_xor_sync(0xffffffffu, v, off);
    if (i == 0) {
        out[(size_t)BN_TOK * D_]     = v * (float)(E_*E_) / (float)B_;
        out[(size_t)BN_TOK * D_ + 1] = g_z2 / (float)BN_TOK;
    }
}

// ---------------- fp16 mma GEMM: BM=64 BN=128 BK=32, 4 warps (2x2), warp 32x64 ----------------
// ldmatrix fragment loads (12 ldmatrix.x4 per k-iter)
#define PA 40   // pitch in halves (80 bytes); 8-row blocks at this pitch are bank-conflict-free

template<bool IS_G1, int OCC>
__global__ void __launch_bounds__(128, OCC) k_mma(const float* __restrict__ bias,
                                                  float* __restrict__ outp)
{
    constexpr int KDIM  = IS_G1 ? D_ : H_;
    constexpr int ITERS = KDIM / 32;
    constexpr int AS_H = 64*PA, BS_H = 128*PA;

    __shared__ __align__(16) __half As[3*AS_H];
    __shared__ __align__(16) __half Bs[3*BS_H];
    __shared__ int tok[64];

    int be = blockIdx.z, b = be >> 3, e = be & 7;
    int m0 = blockIdx.y * 64, n0 = blockIdx.x * 128;
    int tid = threadIdx.x, lane = tid & 31, wid = tid >> 5;

    // skip fully-empty capacity tiles
    if (__ldg(&g_cnt[be]) <= m0) return;

    if (tid < 64) tok[tid] = g_s2t[be*C_ + m0 + tid];
    __syncthreads();

    int ar0 = tid >> 2, ar1 = ar0 + 32, akc = tid & 3;
    int br0 = tid >> 2, bkc = tid & 3;

    const __half* aS0; const __half* aS1; int az0, az1;
    if (IS_G1) {
        int t0 = tok[ar0], t1 = tok[ar1];
        aS0 = (t0 >= 0) ? g_xh + ((size_t)(b*N_ + t0) * D_ + akc*8) : g_xh;
        aS1 = (t1 >= 0) ? g_xh + ((size_t)(b*N_ + t1) * D_ + akc*8) : g_xh;
        az0 = (t0 >= 0) ? 16 : 0;  az1 = (t1 >= 0) ? 16 : 0;
    } else {
        int t0 = tok[ar0], t1 = tok[ar1];
        aS0 = g_Yh + ((size_t)be*C_ + m0 + ar0) * H_ + akc*8;
        aS1 = g_Yh + ((size_t)be*C_ + m0 + ar1) * H_ + akc*8;
        az0 = (t0 >= 0) ? 16 : 0;  az1 = (t1 >= 0) ? 16 : 0;
    }
    const __half* wt = IS_G1 ? g_w1t : g_w2t;
    const __half* wbase = wt + (size_t)e * (IS_G1 ? (size_t)H_*D_ : (size_t)D_*H_)
                        + (size_t)(n0 + br0) * KDIM + bkc*8;

    unsigned saAs = (unsigned)__cvta_generic_to_shared(As);
    unsigned saBs = (unsigned)__cvta_generic_to_shared(Bs);
    unsigned saA0 = saAs + (ar0*PA + akc*8)*2;
    unsigned saA1 = saAs + (ar1*PA + akc*8)*2;
    unsigned saB0 = saBs + (br0*PA + bkc*8)*2;
    constexpr unsigned A_ST = AS_H*2, B_ST = BS_H*2;

    auto fill = [&](int st, int k0) {
        cp16(saA0 + st*A_ST, aS0 + k0, az0);
        cp16(saA1 + st*A_ST, aS1 + k0, az1);
#pragma unroll
        for (int j = 0; j < 4; j++)
            cp16(saB0 + st*B_ST + j*32*PA*2, wbase + (size_t)32*j*KDIM + k0, 16);
        cpcommit();
    };

    float acc[2][8][4];
#pragma unroll
    for (int i = 0; i < 2; i++)
#pragma unroll
        for (int j = 0; j < 8; j++)
#pragma unroll
            for (int k = 0; k < 4; k++) acc[i][j][k] = 0.f;

    fill(0, 0);
    fill(1, 32);

    int wm = wid & 1, wn = wid >> 1;

    unsigned offA = ((unsigned)((lane & 7) + ((lane >> 3) & 1) * 8) * PA
                   + (unsigned)((lane >> 4) & 1) * 8) * 2;
    unsigned offB = ((unsigned)((lane & 7) + ((lane >> 4) & 1) * 8) * PA
                   + (unsigned)((lane >> 3) & 1) * 8) * 2;

    for (int it = 0; it < ITERS; ++it) {
        int cur = it % 3;
        cpwait<1>();
        __syncthreads();

        int nxt = it + 2;
        if (nxt < ITERS) fill(nxt % 3, nxt * 32);
        else cpcommit();

        unsigned baseA = saAs + cur*A_ST + offA;
        unsigned baseB = saBs + cur*B_ST + offB;
#pragma unroll
        for (int s = 0; s < 2; s++) {
            unsigned a[2][4], bf[8][2];
            unsigned ks = (unsigned)(s*16) * 2;
#pragma unroll
            for (int mt = 0; mt < 2; mt++) {
                unsigned ad = baseA + (unsigned)((wm*32 + mt*16) * PA) * 2 + ks;
                ldsm4(a[mt][0], a[mt][1], a[mt][2], a[mt][3], ad);
            }
#pragma unroll
            for (int j = 0; j < 4; j++) {
                unsigned bd = baseB + (unsigned)((wn*64 + j*16) * PA) * 2 + ks;
                ldsm4(bf[2*j][0], bf[2*j][1], bf[2*j+1][0], bf[2*j+1][1], bd);
            }
#pragma unroll
            for (int mt = 0; mt < 2; mt++)
#pragma unroll
                for (int nt = 0; nt < 8; nt++) mma16(acc[mt][nt], a[mt], bf[nt]);
        }
    }

    // ---------------- epilogue ----------------
    int gq = lane >> 2, t4 = lane & 3;
    if (IS_G1) {
#pragma unroll
        for (int mt = 0; mt < 2; mt++) {
            int r1 = m0 + wm*32 + mt*16 + gq, r2 = r1 + 8;
#pragma unroll
            for (int nt = 0; nt < 8; nt++) {
                int gn = n0 + wn*64 + nt*8 + 2*t4;
                float2 bv = *(const float2*)&bias[(size_t)e*H_ + gn];
                __half2 v1, v2;
                v1.x = __float2half(gelu_tanh(acc[mt][nt][0] + bv.x));
                v1.y = __float2half(gelu_tanh(acc[mt][nt][1] + bv.y));
                v2.x = __float2half(gelu_tanh(acc[mt][nt][2] + bv.x));
                v2.y = __float2half(gelu_tanh(acc[mt][nt][3] + bv.y));
                *(__half2*)&g_Yh[((size_t)be*C_ + r1)*H_ + gn] = v1;
                *(__half2*)&g_Yh[((size_t)be*C_ + r2)*H_ + gn] = v2;
            }
        }
    } else {
#pragma unroll
        for (int mt = 0; mt < 2; mt++) {
            int r = wm*32 + mt*16 + gq;
            int tk1 = tok[r], tk2 = tok[r + 8];
            float gv1 = (tk1 >= 0) ? g_gate[b*N_ + tk1] : 0.f;
            float gv2 = (tk2 >= 0) ? g_gate[b*N_ + tk2] : 0.f;
#pragma unroll
            for (int nt = 0; nt < 8; nt++) {
                int gn = n0 + wn*64 + nt*8 + 2*t4;
                float2 bv = *(const float2*)&bias[(size_t)e*D_ + gn];
                if (tk1 >= 0) {
                    float2 v = { gv1*(acc[mt][nt][0] + bv.x), gv1*(acc[mt][nt][1] + bv.y) };
                    *(float2*)&outp[((size_t)(b*N_ + tk1))*D_ + gn] = v;
                }
                if (tk2 >= 0) {
                    float2 v = { gv2*(acc[mt][nt][2] + bv.x), gv2*(acc[mt][nt][3] + bv.y) };
                    *(float2*)&outp[((size_t)(b*N_ + tk2))*D_ + gn] = v;
                }
            }
        }
    }
}

// ---------------- launch: R12 fork-join (proven champion) ----------------
extern "C" void kernel_launch(void* const* d_in, const int* in_sizes, int n_in,
                              void* d_out, int out_size) {
    const float* x  = (const float*)d_in[0];
    const float* wr = (const float*)d_in[1];
    const float* w1 = (const float*)d_in[2];
    const float* b1 = (const float*)d_in[3];
    const float* w2 = (const float*)d_in[4];
    const float* b2 = (const float*)d_in[5];
    float* out = (float*)d_out;

    static cudaStream_t s1 = nullptr, s2 = nullptr;
    static cudaEvent_t ev0 = nullptr, ev1 = nullptr, ev2 = nullptr;
    if (!s1) {
        cudaStreamCreateWithFlags(&s1, cudaStreamNonBlocking);
        cudaStreamCreateWithFlags(&s2, cudaStreamNonBlocking);
        cudaEventCreateWithFlags(&ev0, cudaEventDisableTiming);
        cudaEventCreateWithFlags(&ev1, cudaEventDisableTiming);
        cudaEventCreateWithFlags(&ev2, cudaEventDisableTiming);
    }

    // fork
    cudaEventRecord(ev0, 0);

    // branch A (s1): weight transposes
    cudaStreamWaitEvent(s1, ev0, 0);
    k_tr1<<<dim3(H_/32, D_/32, E_), 128, 0, s1>>>(w1);
    k_tr2<<<dim3(D_/32, H_/32, E_), 128, 0, s1>>>(w2);
    cudaEventRecord(ev1, s1);

    // branch B (s2): zero the output tensor region
    cudaStreamWaitEvent(s2, ev0, 0);
    cudaMemsetAsync(out, 0, (size_t)BN_TOK * D_ * sizeof(float), s2);
    cudaEventRecord(ev2, s2);

    // main chain (stream 0): routing
    k_init<<<(B_*E_*C_ + 255) / 256, 256>>>();
    k_router<<<BN_TOK/RTOK, 512>>>(x, wr);
    k_scan<<<B_*E_, 32>>>();
    k_final<<<1, 32>>>(out);

    // join
    cudaStreamWaitEvent(0, ev1, 0);
    cudaStreamWaitEvent(0, ev2, 0);

    k_mma<true,  2><<<dim3(H_/128, C_/64, B_*E_), 128>>>(b1, nullptr);
    k_mma<false, 3><<<dim3(D_/128, C_/64, B_*E_), 128>>>(b2, out);
}

// round 16
// speedup vs baseline: 1.0540x; 1.0438x over previous
#include <cuda_runtime.h>
#include <cuda_fp16.h>
#include <math.h>
#include <stdint.h>

#define B_  4
#define N_  2048
#define D_  1024
#define E_  8
#define H_  4096
#define C_  320
#define BN_TOK (B_*N_)

// -------- scratch (device globals: allocation-free) --------
__device__ __half g_Yh[(size_t)B_*E_*C_*H_];   // expert hidden, fp16
__device__ __half g_xh[(size_t)BN_TOK*D_];     // x in fp16
__device__ __half g_w1t[(size_t)E_*H_*D_];     // w1 transposed: [E][H][D] fp16 (K-major)
__device__ __half g_w2t[(size_t)E_*D_*H_];     // w2 transposed: [E][D][H] fp16 (K-major)
__device__ int    g_s2t[B_*E_*C_];
__device__ int    g_cnt[B_*E_];
__device__ float  g_proxy[B_*E_];
__device__ float  g_gate[BN_TOK];
__device__ int    g_idx[BN_TOK];
__device__ float  g_z2;

// ---------------- helpers ----------------
__device__ __forceinline__ void mma16(float c[4], const unsigned a[4], const unsigned b[2]) {
    asm volatile("mma.sync.aligned.m16n8k16.row.col.f32.f16.f16.f32 "
                 "{%0,%1,%2,%3},{%4,%5,%6,%7},{%8,%9},{%0,%1,%2,%3};"
                 : "+f"(c[0]), "+f"(c[1]), "+f"(c[2]), "+f"(c[3])
                 : "r"(a[0]), "r"(a[1]), "r"(a[2]), "r"(a[3]), "r"(b[0]), "r"(b[1]));
}
__device__ __forceinline__ void ldsm4(unsigned& r0, unsigned& r1, unsigned& r2, unsigned& r3,
                                      unsigned addr) {
    asm volatile("ldmatrix.sync.aligned.m8n8.x4.shared.b16 {%0,%1,%2,%3}, [%4];"
                 : "=r"(r0), "=r"(r1), "=r"(r2), "=r"(r3) : "r"(addr));
}
__device__ __forceinline__ void cp16(unsigned saddr, const void* g, int sz) {
    asm volatile("cp.async.cg.shared.global [%0], [%1], 16, %2;"
                 :: "r"(saddr), "l"(g), "r"(sz));
}
__device__ __forceinline__ void cpcommit() { asm volatile("cp.async.commit_group;"); }
template<int n> __device__ __forceinline__ void cpwait() {
    asm volatile("cp.async.wait_group %0;" :: "n"(n));
}
// champion gelu (device tanhf — short MUFU sequence)
__device__ __forceinline__ float gelu_tanh(float v) {
    float v3 = v * v * v;
    return 0.5f * v * (1.f + tanhf(0.7978845608028654f * (v + 0.044715f * v3)));
}

// ---------------- init ----------------
__global__ void k_init() {
    int i = blockIdx.x * blockDim.x + threadIdx.x;
    if (i < B_*E_*C_) g_s2t[i] = -1;
    if (i < B_*E_)    g_proxy[i] = 0.f;
    if (i == 0)       g_z2 = 0.f;
}

// ---------------- weight transposes -> fp16 K-major ----------------
__global__ void __launch_bounds__(128) k_tr1(const float* __restrict__ w) {
    __shared__ float s[32][33];
    int e = blockIdx.z, h0 = blockIdx.x*32, d0 = blockIdx.y*32;
    const float* S = w + (size_t)e * D_ * H_;
    int tid = threadIdx.x;
#pragma unroll
    for (int it = 0; it < 2; it++) {
        int dr = (tid >> 3) + it*16;
        int hc = (tid & 7) * 4;
        float4 v = *(const float4*)&S[(size_t)(d0+dr)*H_ + h0 + hc];
        s[dr][hc] = v.x; s[dr][hc+1] = v.y; s[dr][hc+2] = v.z; s[dr][hc+3] = v.w;
    }
    __syncthreads();
    int hp = tid >> 2, o = tid & 3;
    __align__(16) __half hb[8];
#pragma unroll
    for (int j = 0; j < 8; j++) hb[j] = __float2half(s[o*8 + j][hp]);
    *(uint4*)&g_w1t[(size_t)e*H_*D_ + (size_t)(h0+hp)*D_ + d0 + o*8] = *(uint4*)hb;
}
__global__ void __launch_bounds__(128) k_tr2(const float* __restrict__ w) {
    __shared__ float s[32][33];
    int e = blockIdx.z, d0 = blockIdx.x*32, h0 = blockIdx.y*32;
    const float* S = w + (size_t)e * H_ * D_;
    int tid = threadIdx.x;
#pragma unroll
    for (int it = 0; it < 2; it++) {
        int hr = (tid >> 3) + it*16;
        int dc = (tid & 7) * 4;
        float4 v = *(const float4*)&S[(size_t)(h0+hr)*D_ + d0 + dc];
        s[hr][dc] = v.x; s[hr][dc+1] = v.y; s[hr][dc+2] = v.z; s[hr][dc+3] = v.w;
    }
    __syncthreads();
    int dp = tid >> 2, o = tid & 3;
    __align__(16) __half hb[8];
#pragma unroll
    for (int j = 0; j < 8; j++) hb[j] = __float2half(s[o*8 + j][dp]);
    *(uint4*)&g_w2t[(size_t)e*D_*H_ + (size_t)(d0+dp)*H_ + h0 + o*8] = *(uint4*)hb;
}

// ---------------- router: warp per token, block-aggregated atomics ----------------
#define RTOK 16
__global__ void __launch_bounds__(512) k_router(const float* __restrict__ x,
                                                const float* __restrict__ wr) {
    __shared__ float swr[8][1024];
    __shared__ float sproxy[8];
    __shared__ float sz2;
    int tid = threadIdx.x;
    for (int d = tid; d < 1024; d += 512) {
        float4 a = *(const float4*)&wr[d*8];
        float4 b = *(const float4*)&wr[d*8 + 4];
        swr[0][d] = a.x; swr[1][d] = a.y; swr[2][d] = a.z; swr[3][d] = a.w;
        swr[4][d] = b.x; swr[5][d] = b.y; swr[6][d] = b.z; swr[7][d] = b.w;
    }
    if (tid < 8) sproxy[tid] = 0.f;
    if (tid == 8) sz2 = 0.f;
    __syncthreads();

    int warp = tid >> 5, lane = tid & 31;
    int t = blockIdx.x * RTOK + warp;
    int b = t / N_;
    const float* xr = x + (size_t)t * D_;
    __half* xtr = g_xh + (size_t)t * D_;

    float acc[8];
#pragma unroll
    for (int e = 0; e < 8; e++) acc[e] = 0.f;
#pragma unroll
    for (int i = 0; i < 8; i++) {
        int d = i*128 + lane*4;
        float4 xv = __ldg((const float4*)(xr + d));
        __align__(8) __half2 hh[2];
        hh[0] = __floats2half2_rn(xv.x, xv.y);
        hh[1] = __floats2half2_rn(xv.z, xv.w);
        *(uint2*)(xtr + d) = *(uint2*)hh;
#pragma unroll
        for (int e = 0; e < 8; e++) {
            float4 w = *(const float4*)&swr[e][d];
            acc[e] += xv.x*w.x + xv.y*w.y + xv.z*w.z + xv.w*w.w;
        }
    }
#pragma unroll
    for (int e = 0; e < 8; e++)
#pragma unroll
        for (int off = 16; off > 0; off >>= 1)
            acc[e] += __shfl_xor_sync(0xffffffffu, acc[e], off);

    if (lane == 0) {
        float maxl = acc[0]; int amax = 0;
#pragma unroll
        for (int e = 1; e < 8; e++) if (acc[e] > maxl) { maxl = acc[e]; amax = e; }
        float sum = 0.f, p[8];
#pragma unroll
        for (int e = 0; e < 8; e++) { p[e] = expf(acc[e] - maxl); sum += p[e]; }
        float inv = 1.f / sum;
        float z = maxl + logf(sum);
#pragma unroll
        for (int e = 0; e < 8; e++) atomicAdd(&sproxy[e], p[e] * inv);
        atomicAdd(&sz2, z * z);
        g_idx[t]  = amax;
        g_gate[t] = p[amax] * inv;
    }
    __syncthreads();
    if (tid < 8)  atomicAdd(&g_proxy[b*8 + tid], sproxy[tid]);
    if (tid == 8) atomicAdd(&g_z2, sz2);
}

// ---------------- capacity scan ----------------
__global__ void k_scan() {
    int be = blockIdx.x;
    int b = be / E_, e = be % E_;
    int lane = threadIdx.x;
    unsigned lt = (1u << lane) - 1u;
    int base = 0;
    for (int n0 = 0; n0 < N_; n0 += 256) {
        int v[8];
#pragma unroll
        for (int u = 0; u < 8; u++) v[u] = __ldg(&g_idx[b*N_ + n0 + u*32 + lane]);
#pragma unroll
        for (int u = 0; u < 8; u++) {
            int pred = (v[u] == e);
            unsigned bal = __ballot_sync(0xffffffffu, pred);
            if (pred) {
                int slot = base + __popc(bal & lt);
                if (slot < C_) g_s2t[be*C_ + slot] = n0 + u*32 + lane;
            }
            base += __popc(bal);
        }
    }
    if (lane == 0) g_cnt[be] = base;
}

// ---------------- scalar losses (parallel) ----------------
__global__ void k_final(float* __restrict__ out) {
    int i = threadIdx.x;
    float v = ((float)g_cnt[i] / (float)N_) * (g_proxy[i] / (float)N_);
#pragma unroll
    for (int off = 16; off > 0; off >>= 1) v += __shfl_xor_sync(0xffffffffu, v, off);
    if (i == 0) {
        out[(size_t)BN_TOK * D_]     = v * (float)(E_*E_) / (float)B_;
        out[(size_t)BN_TOK * D_ + 1] = g_z2 / (float)BN_TOK;
    }
}

// ---------------- fp16 mma GEMM: BM=64 BN=128 BK=32, 4 warps (2x2), warp 32x64 ----------------
// ldmatrix fragment loads; 4-stage cp.async pipeline (2 groups in flight)
#define PA 40   // pitch in halves (80 bytes)

template<bool IS_G1, int OCC>
__global__ void __launch_bounds__(128, OCC) k_mma(const float* __restrict__ bias,
                                                  float* __restrict__ outp)
{
    constexpr int KDIM  = IS_G1 ? D_ : H_;
    constexpr int ITERS = KDIM / 32;
    constexpr int AS_H = 64*PA, BS_H = 128*PA;

    __shared__ __align__(16) __half As[4*AS_H];
    __shared__ __align__(16) __half Bs[4*BS_H];
    __shared__ int tok[64];

    int be = blockIdx.z, b = be >> 3, e = be & 7;
    int m0 = blockIdx.y * 64, n0 = blockIdx.x * 128;
    int tid = threadIdx.x, lane = tid & 31, wid = tid >> 5;

    // skip fully-empty capacity tiles
    if (__ldg(&g_cnt[be]) <= m0) return;

    if (tid < 64) tok[tid] = g_s2t[be*C_ + m0 + tid];
    __syncthreads();

    int ar0 = tid >> 2, ar1 = ar0 + 32, akc = tid & 3;
    int br0 = tid >> 2, bkc = tid & 3;

    const __half* aS0; const __half* aS1; int az0, az1;
    if (IS_G1) {
        int t0 = tok[ar0], t1 = tok[ar1];
        aS0 = (t0 >= 0) ? g_xh + ((size_t)(b*N_ + t0) * D_ + akc*8) : g_xh;
        aS1 = (t1 >= 0) ? g_xh + ((size_t)(b*N_ + t1) * D_ + akc*8) : g_xh;
        az0 = (t0 >= 0) ? 16 : 0;  az1 = (t1 >= 0) ? 16 : 0;
    } else {
        int t0 = tok[ar0], t1 = tok[ar1];
        aS0 = g_Yh + ((size_t)be*C_ + m0 + ar0) * H_ + akc*8;
        aS1 = g_Yh + ((size_t)be*C_ + m0 + ar1) * H_ + akc*8;
        az0 = (t0 >= 0) ? 16 : 0;  az1 = (t1 >= 0) ? 16 : 0;
    }
    const __half* wt = IS_G1 ? g_w1t : g_w2t;
    const __half* wbase = wt + (size_t)e * (IS_G1 ? (size_t)H_*D_ : (size_t)D_*H_)
                        + (size_t)(n0 + br0) * KDIM + bkc*8;

    unsigned saAs = (unsigned)__cvta_generic_to_shared(As);
    unsigned saBs = (unsigned)__cvta_generic_to_shared(Bs);
    unsigned saA0 = saAs + (ar0*PA + akc*8)*2;
    unsigned saA1 = saAs + (ar1*PA + akc*8)*2;
    unsigned saB0 = saBs + (br0*PA + bkc*8)*2;
    constexpr unsigned A_ST = AS_H*2, B_ST = BS_H*2;

    auto fill = [&](int st, int k0) {
        cp16(saA0 + st*A_ST, aS0 + k0, az0);
        cp16(saA1 + st*A_ST, aS1 + k0, az1);
#pragma unroll
        for (int j = 0; j < 4; j++)
            cp16(saB0 + st*B_ST + j*32*PA*2, wbase + (size_t)32*j*KDIM + k0, 16);
        cpcommit();
    };

    float acc[2][8][4];
#pragma unroll
    for (int i = 0; i < 2; i++)
#pragma unroll
        for (int j = 0; j < 8; j++)
#pragma unroll
            for (int k = 0; k < 4; k++) acc[i][j][k] = 0.f;

    fill(0, 0);
    fill(1, 32);
    fill(2, 64);

    int wm = wid & 1, wn = wid >> 1;

    unsigned offA = ((unsigned)((lane & 7) + ((lane >> 3) & 1) * 8) * PA
                   + (unsigned)((lane >> 4) & 1) * 8) * 2;
    unsigned offB = ((unsigned)((lane & 7) + ((lane >> 4) & 1) * 8) * PA
                   + (unsigned)((lane >> 3) & 1) * 8) * 2;

    for (int it = 0; it < ITERS; ++it) {
        int cur = it & 3;
        cpwait<2>();
        __syncthreads();

        int nxt = it + 3;
        if (nxt < ITERS) fill(nxt & 3, nxt * 32);
        else cpcommit();

        unsigned baseA = saAs + cur*A_ST + offA;
        unsigned baseB = saBs + cur*B_ST + offB;
#pragma unroll
        for (int s = 0; s < 2; s++) {
            unsigned a[2][4], bf[8][2];
            unsigned ks = (unsigned)(s*16) * 2;
#pragma unroll
            for (int mt = 0; mt < 2; mt++) {
                unsigned ad = baseA + (unsigned)((wm*32 + mt*16) * PA) * 2 + ks;
                ldsm4(a[mt][0], a[mt][1], a[mt][2], a[mt][3], ad);
            }
#pragma unroll
            for (int j = 0; j < 4; j++) {
                unsigned bd = baseB + (unsigned)((wn*64 + j*16) * PA) * 2 + ks;
                ldsm4(bf[2*j][0], bf[2*j][1], bf[2*j+1][0], bf[2*j+1][1], bd);
            }
#pragma unroll
            for (int mt = 0; mt < 2; mt++)
#pragma unroll
                for (int nt = 0; nt < 8; nt++) mma16(acc[mt][nt], a[mt], bf[nt]);
        }
    }

    // ---------------- epilogue ----------------
    int gq = lane >> 2, t4 = lane & 3;
    if (IS_G1) {
#pragma unroll
        for (int mt = 0; mt < 2; mt++) {
            int r1 = m0 + wm*32 + mt*16 + gq, r2 = r1 + 8;
#pragma unroll
            for (int nt = 0; nt < 8; nt++) {
                int gn = n0 + wn*64 + nt*8 + 2*t4;
                float2 bv = *(const float2*)&bias[(size_t)e*H_ + gn];
                __half2 v1, v2;
                v1.x = __float2half(gelu_tanh(acc[mt][nt][0] + bv.x));
                v1.y = __float2half(gelu_tanh(acc[mt][nt][1] + bv.y));
                v2.x = __float2half(gelu_tanh(acc[mt][nt][2] + bv.x));
                v2.y = __float2half(gelu_tanh(acc[mt][nt][3] + bv.y));
                *(__half2*)&g_Yh[((size_t)be*C_ + r1)*H_ + gn] = v1;
                *(__half2*)&g_Yh[((size_t)be*C_ + r2)*H_ + gn] = v2;
            }
        }
    } else {
#pragma unroll
        for (int mt = 0; mt < 2; mt++) {
            int r = wm*32 + mt*16 + gq;
            int tk1 = tok[r], tk2 = tok[r + 8];
            float gv1 = (tk1 >= 0) ? g_gate[b*N_ + tk1] : 0.f;
            float gv2 = (tk2 >= 0) ? g_gate[b*N_ + tk2] : 0.f;
#pragma unroll
            for (int nt = 0; nt < 8; nt++) {
                int gn = n0 + wn*64 + nt*8 + 2*t4;
                float2 bv = *(const float2*)&bias[(size_t)e*D_ + gn];
                if (tk1 >= 0) {
                    float2 v = { gv1*(acc[mt][nt][0] + bv.x), gv1*(acc[mt][nt][1] + bv.y) };
                    *(float2*)&outp[((size_t)(b*N_ + tk1))*D_ + gn] = v;
                }
                if (tk2 >= 0) {
                    float2 v = { gv2*(acc[mt][nt][2] + bv.x), gv2*(acc[mt][nt][3] + bv.y) };
                    *(float2*)&outp[((size_t)(b*N_ + tk2))*D_ + gn] = v;
                }
            }
        }
    }
}

// ---------------- launch: R12 fork-join (proven champion) ----------------
extern "C" void kernel_launch(void* const* d_in, const int* in_sizes, int n_in,
                              void* d_out, int out_size) {
    const float* x  = (const float*)d_in[0];
    const float* wr = (const float*)d_in[1];
    const float* w1 = (const float*)d_in[2];
    const float* b1 = (const float*)d_in[3];
    const float* w2 = (const float*)d_in[4];
    const float* b2 = (const float*)d_in[5];
    float* out = (float*)d_out;

    static cudaStream_t s1 = nullptr, s2 = nullptr;
    static cudaEvent_t ev0 = nullptr, ev1 = nullptr, ev2 = nullptr;
    if (!s1) {
        cudaStreamCreateWithFlags(&s1, cudaStreamNonBlocking);
        cudaStreamCreateWithFlags(&s2, cudaStreamNonBlocking);
        cudaEventCreateWithFlags(&ev0, cudaEventDisableTiming);
        cudaEventCreateWithFlags(&ev1, cudaEventDisableTiming);
        cudaEventCreateWithFlags(&ev2, cudaEventDisableTiming);
    }

    // fork
    cudaEventRecord(ev0, 0);

    // branch A (s1): weight transposes
    cudaStreamWaitEvent(s1, ev0, 0);
    k_tr1<<<dim3(H_/32, D_/32, E_), 128, 0, s1>>>(w1);
    k_tr2<<<dim3(D_/32, H_/32, E_), 128, 0, s1>>>(w2);
    cudaEventRecord(ev1, s1);

    // branch B (s2): zero the output tensor region
    cudaStreamWaitEvent(s2, ev0, 0);
    cudaMemsetAsync(out, 0, (size_t)BN_TOK * D_ * sizeof(float), s2);
    cudaEventRecord(ev2, s2);

    // main chain (stream 0): routing
    k_init<<<(B_*E_*C_ + 255) / 256, 256>>>();
    k_router<<<BN_TOK/RTOK, 512>>>(x, wr);
    k_scan<<<B_*E_, 32>>>();
    k_final<<<1, 32>>>(out);

    // join
    cudaStreamWaitEvent(0, ev1, 0);
    cudaStreamWaitEvent(0, ev2, 0);

    k_mma<true,  2><<<dim3(H_/128, C_/64, B_*E_), 128>>>(b1, nullptr);
    k_mma<false, 3><<<dim3(D_/128, C_/64, B_*E_), 128>>>(b2, out);
}